// round 3
// baseline (speedup 1.0000x reference)
#include <cuda_runtime.h>

#define D      512
#define W      5
#define TPB    128
#define DV4    (D / 4)
#define MAX_TIME_ROWS 512

// Scratch: precomputed sin/cos of the time table (row-major [rows][D]).
__device__ float g_sin[MAX_TIME_ROWS * D];
__device__ float g_cos[MAX_TIME_ROWS * D];

__global__ void trig_kernel(const float* __restrict__ tt, int n) {
    int i = blockIdx.x * blockDim.x + threadIdx.x;
    if (i < n) {
        float s, c;
        sincosf(tt[i], &s, &c);
        g_sin[i] = s;
        g_cos[i] = c;
    }
}

__global__ __launch_bounds__(TPB) void contxe_kernel(
    const int*   __restrict__ h_i,
    const int*   __restrict__ t_i,
    const int*   __restrict__ r_i,
    const int*   __restrict__ d_i,
    const float* __restrict__ eEr,
    const float* __restrict__ eEi,
    const float* __restrict__ eRr,
    const float* __restrict__ eRi,
    float*       __restrict__ out,
    int n_day)
{
    const int b    = blockIdx.x;
    const int tid  = threadIdx.x;
    const int lane = tid & 31;
    const int warp = tid >> 5;

    __shared__ float4 sh_s[W * TPB];   // 10 KB
    __shared__ float4 sh_c[W * TPB];   // 10 KB
    __shared__ float  red[4][20];
    __shared__ float  sh_w[20];
    __shared__ float  partial[4];

    const int h = h_i[b];
    const int t = t_i[b];
    const int r = r_i[b];
    const int d = d_i[b];

    // Stage the 5 (sin, cos) rows for this window into smem.
    const float4* sT = (const float4*)g_sin;
    const float4* cT = (const float4*)g_cos;
    #pragma unroll
    for (int w = 0; w < W; w++) {
        int row = d - (W - 1 - w);
        if (row < 0) row = n_day;
        sh_s[w * TPB + tid] = sT[row * DV4 + tid];
        sh_c[w * TPB + tid] = cT[row * DV4 + tid];
    }

    // Embedding gathers (coalesced: each CTA reads a full row as 128 float4s).
    const float4 hr  = ((const float4*)(eEr + (size_t)h * D))[tid];
    const float4 hi4 = ((const float4*)(eEi + (size_t)h * D))[tid];
    const float4 tr  = ((const float4*)(eEr + (size_t)t * D))[tid];
    const float4 ti4 = ((const float4*)(eEi + (size_t)t * D))[tid];
    const float4 rr  = ((const float4*)(eRr + (size_t)r * D))[tid];
    const float4 ri4 = ((const float4*)(eRi + (size_t)r * D))[tid];

    const float* hrp = (const float*)&hr;
    const float* hip = (const float*)&hi4;
    const float* trp = (const float*)&tr;
    const float* tip = (const float*)&ti4;
    const float* rrp = (const float*)&rr;
    const float* rip = (const float*)&ri4;

    __syncthreads();

    // ---- Pass 1: 20 attention-score dot products ----
    float acc[20];
    #pragma unroll
    for (int k = 0; k < 20; k++) acc[k] = 0.0f;

    #pragma unroll
    for (int w = 0; w < W; w++) {
        float4 s4 = sh_s[w * TPB + tid];
        float4 c4 = sh_c[w * TPB + tid];
        const float* sp = (const float*)&s4;
        const float* cp = (const float*)&c4;
        #pragma unroll
        for (int k = 0; k < 4; k++) {
            float s = sp[k], c = cp[k];
            float hre = fmaf(hrp[k], c, -hip[k] * s);
            float him = fmaf(hrp[k], s,  hip[k] * c);
            float tre = fmaf(trp[k], c, -tip[k] * s);
            float tim = fmaf(trp[k], s,  tip[k] * c);
            acc[0 * W + w] = fmaf(rrp[k], hre, acc[0 * W + w]);
            acc[1 * W + w] = fmaf(rip[k], him, acc[1 * W + w]);
            acc[2 * W + w] = fmaf(rrp[k], tre, acc[2 * W + w]);
            acc[3 * W + w] = fmaf(rip[k], tim, acc[3 * W + w]);
        }
    }

    // Warp reduce each of the 20 accumulators.
    #pragma unroll
    for (int k = 0; k < 20; k++) {
        float v = acc[k];
        v += __shfl_xor_sync(0xffffffffu, v, 16);
        v += __shfl_xor_sync(0xffffffffu, v, 8);
        v += __shfl_xor_sync(0xffffffffu, v, 4);
        v += __shfl_xor_sync(0xffffffffu, v, 2);
        v += __shfl_xor_sync(0xffffffffu, v, 1);
        if (lane == 0) red[warp][k] = v;
    }
    __syncthreads();

    // 4 threads each do one 5-way softmax.
    if (tid < 4) {
        float sc[W];
        float m = -1e30f;
        #pragma unroll
        for (int w = 0; w < W; w++) {
            sc[w] = red[0][tid * W + w] + red[1][tid * W + w]
                  + red[2][tid * W + w] + red[3][tid * W + w];
            m = fmaxf(m, sc[w]);
        }
        float sum = 0.0f;
        #pragma unroll
        for (int w = 0; w < W; w++) {
            sc[w] = expf(sc[w] - m);
            sum += sc[w];
        }
        float inv = 1.0f / sum;
        #pragma unroll
        for (int w = 0; w < W; w++) sh_w[tid * W + w] = sc[w] * inv;
    }
    __syncthreads();

    // ---- Pass 2: weighted sums + L1 score ----
    float yre[4] = {0, 0, 0, 0};
    float yim[4] = {0, 0, 0, 0};
    float zre[4] = {0, 0, 0, 0};
    float zim[4] = {0, 0, 0, 0};

    #pragma unroll
    for (int w = 0; w < W; w++) {
        float wa_r = sh_w[0 * W + w];
        float wa_i = sh_w[1 * W + w];
        float wb_r = sh_w[2 * W + w];
        float wb_i = sh_w[3 * W + w];
        float4 s4 = sh_s[w * TPB + tid];
        float4 c4 = sh_c[w * TPB + tid];
        const float* sp = (const float*)&s4;
        const float* cp = (const float*)&c4;
        #pragma unroll
        for (int k = 0; k < 4; k++) {
            float s = sp[k], c = cp[k];
            float hre = fmaf(hrp[k], c, -hip[k] * s);
            float him = fmaf(hrp[k], s,  hip[k] * c);
            float tre = fmaf(trp[k], c, -tip[k] * s);
            float tim = fmaf(trp[k], s,  tip[k] * c);
            yre[k] = fmaf(wa_r, hre, yre[k]);
            yim[k] = fmaf(wa_i, him, yim[k]);
            zre[k] = fmaf(wb_r, tre, zre[k]);
            zim[k] = fmaf(wb_i, tim, zim[k]);
        }
    }

    float local = 0.0f;
    #pragma unroll
    for (int k = 0; k < 4; k++) {
        local += fabsf(yre[k] + rrp[k] - zre[k]);
        local += fabsf(yim[k] + rip[k] + zim[k]);
    }

    local += __shfl_xor_sync(0xffffffffu, local, 16);
    local += __shfl_xor_sync(0xffffffffu, local, 8);
    local += __shfl_xor_sync(0xffffffffu, local, 4);
    local += __shfl_xor_sync(0xffffffffu, local, 2);
    local += __shfl_xor_sync(0xffffffffu, local, 1);
    if (lane == 0) partial[warp] = local;
    __syncthreads();

    if (tid == 0) {
        out[b] = partial[0] + partial[1] + partial[2] + partial[3];
    }
}

extern "C" void kernel_launch(void* const* d_in, const int* in_sizes, int n_in,
                              void* d_out, int out_size) {
    const int*   h_i = (const int*)  d_in[0];
    const int*   t_i = (const int*)  d_in[1];
    const int*   r_i = (const int*)  d_in[2];
    const int*   d_i = (const int*)  d_in[3];
    const float* eEr = (const float*)d_in[4];
    const float* eEi = (const float*)d_in[5];
    const float* eRr = (const float*)d_in[6];
    const float* eRi = (const float*)d_in[7];
    const float* tt  = (const float*)d_in[8];

    const int B          = in_sizes[0];
    const int time_elems = in_sizes[8];
    const int time_rows  = time_elems / D;
    const int n_day      = time_rows - 2;

    trig_kernel<<<(time_elems + 255) / 256, 256>>>(tt, time_elems);
    contxe_kernel<<<B, TPB>>>(h_i, t_i, r_i, d_i, eEr, eEi, eRr, eRi,
                              (float*)d_out, n_day);
}

// round 4
// speedup vs baseline: 1.1559x; 1.1559x over previous
#include <cuda_runtime.h>

#define D      512
#define W      5
#define TPB    128
#define DV4    (D / 4)
#define MAX_TIME_ROWS 512

// Precomputed sin/cos of the time table (row-major [rows][D]). L2-resident (1.5MB).
__device__ float g_sin[MAX_TIME_ROWS * D];
__device__ float g_cos[MAX_TIME_ROWS * D];

__global__ void trig_kernel(const float* __restrict__ tt, int n) {
    int i = blockIdx.x * blockDim.x + threadIdx.x;
    if (i < n) {
        float s, c;
        sincosf(tt[i], &s, &c);
        g_sin[i] = s;
        g_cos[i] = c;
    }
}

__global__ __launch_bounds__(TPB) void contxe_kernel(
    const int*   __restrict__ h_i,
    const int*   __restrict__ t_i,
    const int*   __restrict__ r_i,
    const int*   __restrict__ d_i,
    const float* __restrict__ eEr,
    const float* __restrict__ eEi,
    const float* __restrict__ eRr,
    const float* __restrict__ eRi,
    float*       __restrict__ out,
    int n_day)
{
    const int b    = blockIdx.x;
    const int tid  = threadIdx.x;
    const int lane = tid & 31;
    const int warp = tid >> 5;

    __shared__ float acc_s[TPB * 20];   // 10240 B, row = 20 floats (80B, 16B-aligned)
    __shared__ float sums[20];
    __shared__ float sh_w[20];
    __shared__ float partial[4];

    const int h = h_i[b];
    const int t = t_i[b];
    const int r = r_i[b];
    const int d = d_i[b];

    // ---- Trig rows for this window: straight into registers (L2 hits) ----
    float4 S[W], C[W];
    const float4* sT = (const float4*)g_sin;
    const float4* cT = (const float4*)g_cos;
    #pragma unroll
    for (int w = 0; w < W; w++) {
        int row = d - (W - 1 - w);
        if (row < 0) row = n_day;
        S[w] = sT[row * DV4 + tid];
        C[w] = cT[row * DV4 + tid];
    }

    // ---- Embedding gathers (coalesced full rows) ----
    const float4 hr4 = ((const float4*)(eEr + (size_t)h * D))[tid];
    const float4 hi4 = ((const float4*)(eEi + (size_t)h * D))[tid];
    const float4 tr4 = ((const float4*)(eEr + (size_t)t * D))[tid];
    const float4 ti4 = ((const float4*)(eEi + (size_t)t * D))[tid];
    const float4 rr4 = ((const float4*)(eRr + (size_t)r * D))[tid];
    const float4 ri4 = ((const float4*)(eRi + (size_t)r * D))[tid];

    const float* hrp = (const float*)&hr4;
    const float* hip = (const float*)&hi4;
    const float* trp = (const float*)&tr4;
    const float* tip = (const float*)&ti4;
    const float* rrp = (const float*)&rr4;
    const float* rip = (const float*)&ri4;

    // ---- Pass 1: 20 attention-score partial dots via elementwise products ----
    // a_real(w) = (rr*hr)·c_w - (rr*hi)·s_w ;  a_img(w) = (ri*hr)·s_w + (ri*hi)·c_w
    // b_real(w) = (rr*tr)·c_w - (rr*ti)·s_w ;  b_img(w) = (ri*tr)·s_w + (ri*ti)·c_w
    float acc[20];
    #pragma unroll
    for (int j = 0; j < 20; j++) acc[j] = 0.0f;

    #pragma unroll
    for (int k = 0; k < 4; k++) {
        const float p_hr = rrp[k] * hrp[k];
        const float p_hi = rrp[k] * hip[k];
        const float q_hr = rip[k] * hrp[k];
        const float q_hi = rip[k] * hip[k];
        const float p_tr = rrp[k] * trp[k];
        const float p_ti = rrp[k] * tip[k];
        const float q_tr = rip[k] * trp[k];
        const float q_ti = rip[k] * tip[k];
        #pragma unroll
        for (int w = 0; w < W; w++) {
            const float c = ((const float*)&C[w])[k];
            const float s = ((const float*)&S[w])[k];
            acc[0 * W + w] = fmaf(p_hr, c, acc[0 * W + w]);
            acc[0 * W + w] = fmaf(-p_hi, s, acc[0 * W + w]);
            acc[1 * W + w] = fmaf(q_hr, s, acc[1 * W + w]);
            acc[1 * W + w] = fmaf(q_hi, c, acc[1 * W + w]);
            acc[2 * W + w] = fmaf(p_tr, c, acc[2 * W + w]);
            acc[2 * W + w] = fmaf(-p_ti, s, acc[2 * W + w]);
            acc[3 * W + w] = fmaf(q_tr, s, acc[3 * W + w]);
            acc[3 * W + w] = fmaf(q_ti, c, acc[3 * W + w]);
        }
    }

    // ---- Cross-thread reduction: STS.128 dump + conflict-free column sums ----
    {
        float4* rowp = (float4*)(acc_s + tid * 20);
        #pragma unroll
        for (int j = 0; j < 5; j++)
            rowp[j] = make_float4(acc[4 * j], acc[4 * j + 1], acc[4 * j + 2], acc[4 * j + 3]);
    }
    __syncthreads();

    if (tid < 20) {
        // Column tid over 128 rows of stride 20: lanes 0..19 hit distinct banks.
        float v0 = 0.f, v1 = 0.f, v2 = 0.f, v3 = 0.f;
        #pragma unroll
        for (int i = 0; i < TPB; i += 4) {
            v0 += acc_s[(i + 0) * 20 + tid];
            v1 += acc_s[(i + 1) * 20 + tid];
            v2 += acc_s[(i + 2) * 20 + tid];
            v3 += acc_s[(i + 3) * 20 + tid];
        }
        sums[tid] = (v0 + v1) + (v2 + v3);
    }
    __syncthreads();

    // ---- 4 softmaxes over the 5-slot window ----
    if (tid < 4) {
        float sc[W];
        float m = -1e30f;
        #pragma unroll
        for (int w = 0; w < W; w++) {
            sc[w] = sums[tid * W + w];
            m = fmaxf(m, sc[w]);
        }
        float sum = 0.0f;
        #pragma unroll
        for (int w = 0; w < W; w++) {
            sc[w] = expf(sc[w] - m);
            sum += sc[w];
        }
        float inv = 1.0f / sum;
        #pragma unroll
        for (int w = 0; w < W; w++) sh_w[tid * W + w] = sc[w] * inv;
    }
    __syncthreads();

    // ---- Pass 2: fold weights into trig sums, then combine ----
    float wreg[20];
    #pragma unroll
    for (int j = 0; j < 20; j++) wreg[j] = sh_w[j];   // broadcast LDS

    float local = 0.0f;
    #pragma unroll
    for (int k = 0; k < 4; k++) {
        float Ca = 0.f, Sa = 0.f, Cai = 0.f, Sai = 0.f;
        float Cb = 0.f, Sb = 0.f, Cbi = 0.f, Sbi = 0.f;
        #pragma unroll
        for (int w = 0; w < W; w++) {
            const float c = ((const float*)&C[w])[k];
            const float s = ((const float*)&S[w])[k];
            Ca  = fmaf(wreg[0 * W + w], c, Ca);
            Sa  = fmaf(wreg[0 * W + w], s, Sa);
            Cai = fmaf(wreg[1 * W + w], c, Cai);
            Sai = fmaf(wreg[1 * W + w], s, Sai);
            Cb  = fmaf(wreg[2 * W + w], c, Cb);
            Sb  = fmaf(wreg[2 * W + w], s, Sb);
            Cbi = fmaf(wreg[3 * W + w], c, Cbi);
            Sbi = fmaf(wreg[3 * W + w], s, Sbi);
        }
        // y_real = hr*Ca - hi*Sa ; y_img = hr*Sai + hi*Cai
        // z_real = tr*Cb - ti*Sb ; z_img = tr*Sbi + ti*Cbi
        const float y_real = fmaf(hrp[k], Ca, -hip[k] * Sa);
        const float y_img  = fmaf(hrp[k], Sai,  hip[k] * Cai);
        const float z_real = fmaf(trp[k], Cb, -tip[k] * Sb);
        const float z_img  = fmaf(trp[k], Sbi,  tip[k] * Cbi);
        local += fabsf(y_real + rrp[k] - z_real);
        local += fabsf(y_img  + rip[k] + z_img);
    }

    // ---- Final reduction: one value per thread ----
    local += __shfl_xor_sync(0xffffffffu, local, 16);
    local += __shfl_xor_sync(0xffffffffu, local, 8);
    local += __shfl_xor_sync(0xffffffffu, local, 4);
    local += __shfl_xor_sync(0xffffffffu, local, 2);
    local += __shfl_xor_sync(0xffffffffu, local, 1);
    if (lane == 0) partial[warp] = local;
    __syncthreads();

    if (tid == 0) {
        out[b] = (partial[0] + partial[1]) + (partial[2] + partial[3]);
    }
}

extern "C" void kernel_launch(void* const* d_in, const int* in_sizes, int n_in,
                              void* d_out, int out_size) {
    const int*   h_i = (const int*)  d_in[0];
    const int*   t_i = (const int*)  d_in[1];
    const int*   r_i = (const int*)  d_in[2];
    const int*   d_i = (const int*)  d_in[3];
    const float* eEr = (const float*)d_in[4];
    const float* eEi = (const float*)d_in[5];
    const float* eRr = (const float*)d_in[6];
    const float* eRi = (const float*)d_in[7];
    const float* tt  = (const float*)d_in[8];

    const int B          = in_sizes[0];
    const int time_elems = in_sizes[8];
    const int time_rows  = time_elems / D;
    const int n_day      = time_rows - 2;

    trig_kernel<<<(time_elems + 255) / 256, 256>>>(tt, time_elems);
    contxe_kernel<<<B, TPB>>>(h_i, t_i, r_i, d_i, eEr, eEi, eRr, eRi,
                              (float*)d_out, n_day);
}